// round 10
// baseline (speedup 1.0000x reference)
#include <cuda_runtime.h>
#include <cuda_bf16.h>
#include <mma.h>
#include <math.h>
#include <float.h>
#include <stdint.h>

using namespace nvcuda;

namespace {
constexpr int Nn = 4096, Cc = 512, Hh = 128, Tt = 64, Dd = 20, Kt = 10, G = 384;
constexpr int D24 = 24;

constexpr size_t SZ_GX = (size_t)Tt * Nn * G;
constexpr size_t SZ_OUT0 = (size_t)Tt * Nn * Hh;
constexpr size_t SZ_NH = (size_t)Nn * Hh;
constexpr size_t SZ_WT = (size_t)Hh * G;
constexpr size_t SZ_CH = (size_t)Cc * Hh;
constexpr size_t SZ_NC = (size_t)Nn * Cc;
constexpr size_t SZ_BIG = (size_t)Nn * Nn;

constexpr size_t OFF_GX = 0;
constexpr size_t OFF_OUT0 = OFF_GX + SZ_GX;
constexpr size_t OFF_HA = OFF_OUT0 + SZ_OUT0;
constexpr size_t OFF_WT0 = OFF_HA + SZ_NH;
constexpr size_t OFF_WT1 = OFF_WT0 + SZ_WT;
constexpr size_t OFF_WIH1T = OFF_WT1 + SZ_WT;
constexpr size_t OFF_DEN = OFF_WIH1T + SZ_WT;
constexpr size_t OFF_HIDDEN = OFF_DEN + Cc;
constexpr size_t OFF_V1 = OFF_HIDDEN + SZ_CH;
constexpr size_t OFF_LOGITS = OFF_V1 + Cc;
constexpr size_t OFF_CMAX = OFF_LOGITS + SZ_NC;
constexpr size_t OFF_CSUM = OFF_CMAX + Cc;
constexpr size_t OFF_HIDDEN2 = OFF_CSUM + Cc;
constexpr size_t OFF_NY = OFF_HIDDEN2 + SZ_CH;
constexpr size_t OFF_NX = OFF_NY + Cc;
constexpr size_t OFF_C2S = OFF_NX + Nn;
constexpr size_t OFF_PRAW = OFF_C2S + SZ_NC;
constexpr size_t OFF_PSH = OFF_PRAW + SZ_NH;
constexpr size_t OFF_PBACK = OFF_PSH + SZ_NH;
constexpr size_t OFF_OUTPS = OFF_PBACK + SZ_NH;
constexpr size_t OFF_HSH = OFF_OUTPS + SZ_NH;
constexpr size_t OFF_NHS = OFF_HSH + SZ_NH;
constexpr size_t OFF_DIAG = OFF_NHS + Nn;
constexpr size_t OFF_BIG = OFF_DIAG + Nn;
constexpr size_t OFF_TOPV = OFF_BIG + SZ_BIG;
constexpr size_t OFF_HH = OFF_TOPV + (size_t)Nn * Kt;
constexpr size_t OFF_COLSUM = OFF_HH + SZ_NH;
constexpr size_t OFF_V2 = OFF_COLSUM + Nn;
constexpr size_t OFF_NHH = OFF_V2 + Nn;
constexpr size_t OFF_HSIRAW = OFF_NHH + Nn;
constexpr size_t OFF_HSI = OFF_HSIRAW + SZ_NH;
constexpr size_t OFF_HBACK = OFF_HSI + SZ_NH;
constexpr size_t OFF_OUTHS = OFF_HBACK + SZ_NH;
constexpr size_t OFF_OUTIN = OFF_OUTHS + SZ_NH;
constexpr size_t OFF_XT = OFF_OUTIN + SZ_NH;                     // xt24 [T,N,24]
constexpr size_t OFF_WIH0T = OFF_XT + (size_t)Tt * Nn * D24;     // [24][G]
constexpr size_t TOTAL = OFF_WIH0T + (size_t)D24 * G;

// GRU wmma kernel smem: h double buffer + gh staging
constexpr int SMEM_GRU = (2 * 32 * Hh + 32 * G) * 4;  // 81920 bytes
}  // namespace

__device__ float g_buf[TOTAL];
__device__ int g_topi[Nn * Kt];

__device__ __forceinline__ float fsig(float x) {
    return __fdividef(1.f, 1.f + __expf(-x));
}
__device__ __forceinline__ float ftanh(float x) {
    float y;
    asm("tanh.approx.f32 %0, %1;" : "=f"(y) : "f"(x));
    return y;
}
__device__ __forceinline__ float tf32r(float x) {
    float y;
    asm("cvt.rna.tf32.f32 %0, %1;" : "=f"(y) : "f"(x));
    return y;
}

// ---------------------------------------------------------------------------
// prep: transposes (tf32-rounded recurrent + input weights), zero den/colsum
// ---------------------------------------------------------------------------
__global__ void k_prep_all(const float* __restrict__ w0, const float* __restrict__ w1,
                           const float* __restrict__ w2, const float* __restrict__ wi0,
                           float* __restrict__ t0, float* __restrict__ t1,
                           float* __restrict__ t2, float* __restrict__ ti0,
                           float* __restrict__ den, float* __restrict__ colsum) {
    int i = blockIdx.x * blockDim.x + threadIdx.x;
    if (i < G * Hh) {
        int r = i / Hh, c = i % Hh;
        t0[c * G + r] = tf32r(w0[i]);
        t1[c * G + r] = tf32r(w1[i]);
        t2[c * G + r] = w2[i];
    }
    if (i < G * Dd) {
        int r = i / Dd, c = i % Dd;
        ti0[c * G + r] = tf32r(wi0[i]);
    }
    if (i < Cc) den[i] = 0.f;
    if (i < Nn) colsum[i] = 0.f;
}

// x [N, D*T] -> xt24 [T, N, 24] (cols 20..23 zero); zero hh; zero wih0t pad rows
__global__ void k_xt(const float* __restrict__ x, float* __restrict__ xt,
                     float* __restrict__ hh, float* __restrict__ wpad) {
    int i = blockIdx.x * blockDim.x + threadIdx.x;
    if (i < Nn * Tt * D24) {
        int n = i / (Tt * D24);
        int rem = i % (Tt * D24);
        int d = rem / Tt, t = rem % Tt;
        xt[((size_t)t * Nn + n) * D24 + d] =
            (d < Dd) ? x[(size_t)n * (Dd * Tt) + d * Tt + t] : 0.f;
    }
    if (i < (int)SZ_NH) hh[i] = 0.f;
    if (i < 4 * G) wpad[Dd * G + i] = 0.f;  // rows 20..23 of [24][G]
}

// ---------------------------------------------------------------------------
// gx0 = xt24 @ wih0t + bih0  via tf32 wmma. M=T*N, K=24. 64x64 tiles, 4 warps.
// ---------------------------------------------------------------------------
__global__ __launch_bounds__(128, 4) void k_gx0_tf32(
    const float* __restrict__ A,   // [M,24]
    const float* __restrict__ WT,  // [24][G] tf32-rounded, zero-padded rows
    const float* __restrict__ bias, float* __restrict__ Cout) {
    __shared__ float As[64][32];
    __shared__ float bs[16][64];
    int m0 = blockIdx.x * 64;
    int n0 = blockIdx.y * 64;
    int tid = threadIdx.x;
    int warp = tid >> 5;
    for (int e = tid; e < 64 * D24; e += 128)
        As[e / D24][e % D24] = A[(size_t)(m0 + e / D24) * D24 + e % D24];
    for (int e = tid; e < 16 * 64; e += 128) bs[e >> 6][e & 63] = bias[n0 + (e & 63)];
    __syncthreads();
    int wm = (warp >> 1) * 32, wn = (warp & 1) * 32;
    wmma::fragment<wmma::accumulator, 16, 16, 8, float> acc[2][2];
#pragma unroll
    for (int i = 0; i < 2; i++)
#pragma unroll
        for (int jj = 0; jj < 2; jj++)
            wmma::load_matrix_sync(acc[i][jj], &bs[0][wn + jj * 16], 64, wmma::mem_row_major);
#pragma unroll
    for (int kt = 0; kt < 3; kt++) {
        wmma::fragment<wmma::matrix_a, 16, 16, 8, wmma::precision::tf32, wmma::row_major> af[2];
        wmma::fragment<wmma::matrix_b, 16, 16, 8, wmma::precision::tf32, wmma::row_major> bf[2];
#pragma unroll
        for (int i = 0; i < 2; i++) {
            wmma::load_matrix_sync(af[i], &As[wm + i * 16][kt * 8], 32);
#pragma unroll
            for (int e = 0; e < af[i].num_elements; e++)
                af[i].x[e] = wmma::__float_to_tf32(af[i].x[e]);
        }
#pragma unroll
        for (int jj = 0; jj < 2; jj++)
            wmma::load_matrix_sync(bf[jj], WT + (size_t)(kt * 8) * G + n0 + wn + jj * 16, G);
#pragma unroll
        for (int i = 0; i < 2; i++)
#pragma unroll
            for (int jj = 0; jj < 2; jj++)
                wmma::mma_sync(acc[i][jj], af[i], bf[jj], acc[i][jj]);
    }
#pragma unroll
    for (int i = 0; i < 2; i++)
#pragma unroll
        for (int jj = 0; jj < 2; jj++)
            wmma::store_matrix_sync(Cout + (size_t)(m0 + wm + i * 16) * G + n0 + wn + jj * 16,
                                    acc[i][jj], G, wmma::mem_row_major);
}

// ---------------------------------------------------------------------------
// GRU layer via tf32 wmma, persistent over T inside the block.
// grid=128 x 32 rows, 512 threads (16 warps = 2 m-tiles x 8 n-groups).
// Warp owns gate tiles (j, j+128, j+256) of its 16-col group -> gh staged in
// smem, scalar epilogue, double-buffered h.
// ---------------------------------------------------------------------------
__global__ __launch_bounds__(512, 1) void k_gru_wmma(
    const float* __restrict__ gx,   // [T,N,G] input gates incl. b_ih
    const float* __restrict__ wt,   // [128][384] tf32-rounded (global, L1)
    const float* __restrict__ bhh,
    float* __restrict__ out_seq,    // L0: [T,N,H]; L1: null
    float* __restrict__ xh) {       // L1: [N,H]; L0: null
    extern __shared__ float sm[];
    float* hsA = sm;                // [32][128]
    float* hsB = sm + 32 * Hh;      // [32][128]
    float* ghs = sm + 2 * 32 * Hh;  // [32][384]
    int tid = threadIdx.x;
    int warp = tid >> 5;
    int mt = warp >> 3, ng = warp & 7;
    int n0 = blockIdx.x * 32;
    int j = tid & 127, rg = tid >> 7;
    float br = bhh[j], bz = bhh[j + 128], bn = bhh[j + 256];

    for (int e = tid; e < 32 * Hh; e += 512) hsA[e] = 0.f;
    __syncthreads();
    float* hcur = hsA;
    float* hnxt = hsB;

    for (int t = 0; t < Tt; t++) {
        // prefetch this step's input gates (independent of smem state)
        const float* gp = gx + ((size_t)t * Nn + n0) * G;
        float gxr[8], gxz[8], gxn[8];
#pragma unroll
        for (int m = 0; m < 8; m++) {
            int row = rg * 8 + m;
            gxr[m] = gp[row * G + j];
            gxz[m] = gp[row * G + j + 128];
            gxn[m] = gp[row * G + j + 256];
        }

        wmma::fragment<wmma::accumulator, 16, 16, 8, float> acc[3];
#pragma unroll
        for (int g = 0; g < 3; g++) wmma::fill_fragment(acc[g], 0.f);
#pragma unroll
        for (int kt = 0; kt < 16; kt++) {
            wmma::fragment<wmma::matrix_a, 16, 16, 8, wmma::precision::tf32, wmma::row_major> af;
            wmma::load_matrix_sync(af, hcur + (mt * 16) * Hh + kt * 8, Hh);
#pragma unroll
            for (int e = 0; e < af.num_elements; e++)
                af.x[e] = wmma::__float_to_tf32(af.x[e]);
#pragma unroll
            for (int g = 0; g < 3; g++) {
                wmma::fragment<wmma::matrix_b, 16, 16, 8, wmma::precision::tf32, wmma::row_major> bf;
                wmma::load_matrix_sync(bf, wt + (size_t)(kt * 8) * G + g * 128 + ng * 16, G);
                wmma::mma_sync(acc[g], af, bf, acc[g]);
            }
        }
#pragma unroll
        for (int g = 0; g < 3; g++)
            wmma::store_matrix_sync(ghs + (mt * 16) * G + g * 128 + ng * 16, acc[g], G,
                                    wmma::mem_row_major);
        __syncthreads();  // gh ready

        // gate epilogue: 8 rows per thread group; write h_next + optional out
#pragma unroll
        for (int m = 0; m < 8; m++) {
            int row = rg * 8 + m;
            float ghr = ghs[row * G + j];
            float ghz = ghs[row * G + j + 128];
            float ghn = ghs[row * G + j + 256];
            float r = fsig(gxr[m] + ghr + br);
            float z = fsig(gxz[m] + ghz + bz);
            float nc = ftanh(gxn[m] + r * (ghn + bn));
            float hnew = (1.f - z) * nc + z * hcur[row * Hh + j];
            hnxt[row * Hh + j] = hnew;
            if (out_seq) out_seq[((size_t)t * Nn + n0 + row) * Hh + j] = hnew;
        }
        float* tmp = hcur; hcur = hnxt; hnxt = tmp;
        __syncthreads();  // h_next visible + ghs consumed before next store
    }
    if (xh) {
#pragma unroll
        for (int m = 0; m < 8; m++) {
            int row = rg * 8 + m;
            xh[(size_t)(n0 + row) * Hh + j] = hcur[row * Hh + j];
        }
    }
}

// ---------------------------------------------------------------------------
// gx1 = out0 @ wih1T + bih1 via tf32 wmma (unchanged from R5)
// ---------------------------------------------------------------------------
__global__ __launch_bounds__(128, 4) void k_gemm_g3_tf32(
    const float* __restrict__ A, const float* __restrict__ WT,
    const float* __restrict__ bias, float* __restrict__ Cout) {
    __shared__ float As[64][128];
    __shared__ float bs[16][64];
    int m0 = blockIdx.x * 64;
    int n0 = blockIdx.y * 64;
    int tid = threadIdx.x;
    int warp = tid >> 5;
    {
        const float4* s = (const float4*)(A + (size_t)m0 * Hh);
        float4* d = (float4*)As;
        for (int e = tid; e < 64 * 128 / 4; e += 128) d[e] = s[e];
    }
    for (int e = tid; e < 16 * 64; e += 128) bs[e >> 6][e & 63] = bias[n0 + (e & 63)];
    __syncthreads();
    int wm = (warp >> 1) * 32, wn = (warp & 1) * 32;
    wmma::fragment<wmma::accumulator, 16, 16, 8, float> acc[2][2];
#pragma unroll
    for (int i = 0; i < 2; i++)
#pragma unroll
        for (int jj = 0; jj < 2; jj++)
            wmma::load_matrix_sync(acc[i][jj], &bs[0][wn + jj * 16], 64, wmma::mem_row_major);
#pragma unroll
    for (int k = 0; k < Hh; k += 8) {
        wmma::fragment<wmma::matrix_a, 16, 16, 8, wmma::precision::tf32, wmma::row_major> af[2];
        wmma::fragment<wmma::matrix_b, 16, 16, 8, wmma::precision::tf32, wmma::row_major> bf[2];
#pragma unroll
        for (int i = 0; i < 2; i++) {
            wmma::load_matrix_sync(af[i], &As[wm + i * 16][k], 128);
#pragma unroll
            for (int e = 0; e < af[i].num_elements; e++)
                af[i].x[e] = wmma::__float_to_tf32(af[i].x[e]);
        }
#pragma unroll
        for (int jj = 0; jj < 2; jj++) {
            wmma::load_matrix_sync(bf[jj], WT + (size_t)k * G + n0 + wn + jj * 16, G);
#pragma unroll
            for (int e = 0; e < bf[jj].num_elements; e++)
                bf[jj].x[e] = wmma::__float_to_tf32(bf[jj].x[e]);
        }
#pragma unroll
        for (int i = 0; i < 2; i++)
#pragma unroll
            for (int jj = 0; jj < 2; jj++)
                wmma::mma_sync(acc[i][jj], af[i], bf[jj], acc[i][jj]);
    }
#pragma unroll
    for (int i = 0; i < 2; i++)
#pragma unroll
        for (int jj = 0; jj < 2; jj++)
            wmma::store_matrix_sync(Cout + (size_t)(m0 + wm + i * 16) * G + n0 + wn + jj * 16,
                                    acc[i][jj], G, wmma::mem_row_major);
}

// den[c] = sum_n cm[n,c]*mv[n]
__global__ void k_den(const float* __restrict__ cm, const float* __restrict__ mv,
                      float* __restrict__ den) {
    int c = blockIdx.x * 128 + threadIdx.x;
    int nb = blockIdx.y;
    float s = 0.f;
    for (int n = nb * 512; n < (nb + 1) * 512; n++) s += cm[(size_t)n * Cc + c] * mv[n];
    atomicAdd(&den[c], s);
}

// Weighted aggregation into [C,H]
__global__ void k_cagg(const float* __restrict__ cm, const float* __restrict__ mv,
                       const float* __restrict__ den, const float* __restrict__ logits,
                       const float* __restrict__ cmax, const float* __restrict__ csum,
                       const float* __restrict__ xh, float* __restrict__ outp,
                       float* __restrict__ aux, int mode) {
    __shared__ float xs[64][Hh];
    __shared__ float cs[64][8];
    __shared__ float red[256];
    int c0 = blockIdx.x * 8;
    int tid = threadIdx.x;
    int h = tid & 127, g = tid >> 7;
    float acc[4] = {0.f, 0.f, 0.f, 0.f};
    for (int nb = 0; nb < Nn; nb += 64) {
        for (int e = tid; e < 64 * Hh; e += 256)
            xs[e >> 7][e & 127] = xh[(size_t)(nb + (e >> 7)) * Hh + (e & 127)];
        for (int e = tid; e < 64 * 8; e += 256) {
            int nn = e >> 3, ci = e & 7;
            int n = nb + nn, c = c0 + ci;
            float coef;
            if (mode == 0) {
                float cv = cm[(size_t)n * Cc + c];
                coef = cv * mv[n] / (den[c] * cv + 1.f);
            } else {
                coef = __expf(logits[(size_t)n * Cc + c] - cmax[c]) / csum[c];
            }
            cs[nn][ci] = coef;
        }
        __syncthreads();
#pragma unroll 4
        for (int nn = 0; nn < 64; nn++) {
            float xv = xs[nn][h];
#pragma unroll
            for (int u = 0; u < 4; u++) acc[u] += cs[nn][g + 2 * u] * xv;
        }
        __syncthreads();
    }
#pragma unroll
    for (int u = 0; u < 4; u++) outp[(size_t)(c0 + g + 2 * u) * Hh + h] = acc[u];
    for (int u = 0; u < 4; u++) {
        red[tid] = (mode == 0) ? acc[u] : acc[u] * acc[u];
        __syncthreads();
        for (int st = 64; st > 0; st >>= 1) {
            if (h < st) red[tid] += red[tid + st];
            __syncthreads();
        }
        if (h == 0) {
            int c = c0 + g + 2 * u;
            aux[c] = (mode == 0) ? ((red[tid] != 0.f) ? 1.f : 0.f) : sqrtf(red[tid]);
        }
        __syncthreads();
    }
}

// Out = A [- B]; nrm = ||row||; diag = ss/max(ss,1e-12)
__global__ void k_subnorm(const float* __restrict__ A, const float* __restrict__ B,
                          float* __restrict__ Out, float* __restrict__ nrm,
                          float* __restrict__ diag) {
    __shared__ float red[128];
    int n = blockIdx.x;
    int tid = threadIdx.x;
    float v = A[(size_t)n * Hh + tid];
    if (B) v -= B[(size_t)n * Hh + tid];
    Out[(size_t)n * Hh + tid] = v;
    red[tid] = v * v;
    __syncthreads();
    for (int st = 64; st > 0; st >>= 1) {
        if (tid < st) red[tid] += red[tid + st];
        __syncthreads();
    }
    if (tid == 0) {
        float ss = red[0];
        nrm[n] = sqrtf(ss);
        if (diag) diag[n] = ss / fmaxf(ss, 1e-12f);
    }
}

// NT GEMM, K=128; flags: 1=cosine-normalize, 2=zero diag
__global__ void k_gemm_nt(const float* __restrict__ A, const float* __restrict__ B,
                          const float* __restrict__ nx, const float* __restrict__ ny,
                          float* __restrict__ Cmat, int Ndim, int flags) {
    __shared__ float As[64][33];
    __shared__ float Bs[64][33];
    int m0 = blockIdx.y * 64, n0 = blockIdx.x * 64;
    int tid = threadIdx.x;
    int ty = tid / 16, tx = tid % 16;
    float acc[4][4];
#pragma unroll
    for (int i = 0; i < 4; i++)
#pragma unroll
        for (int jj = 0; jj < 4; jj++) acc[i][jj] = 0.f;
    for (int kc = 0; kc < Hh; kc += 32) {
        for (int e = tid; e < 64 * 32; e += 256) {
            int r = e / 32, c = e % 32;
            As[r][c] = A[(size_t)(m0 + r) * Hh + kc + c];
            Bs[r][c] = B[(size_t)(n0 + r) * Hh + kc + c];
        }
        __syncthreads();
#pragma unroll 8
        for (int kk = 0; kk < 32; kk++) {
            float a[4], b[4];
#pragma unroll
            for (int i = 0; i < 4; i++) a[i] = As[ty * 4 + i][kk];
#pragma unroll
            for (int jj = 0; jj < 4; jj++) b[jj] = Bs[tx * 4 + jj][kk];
#pragma unroll
            for (int i = 0; i < 4; i++)
#pragma unroll
                for (int jj = 0; jj < 4; jj++) acc[i][jj] += a[i] * b[jj];
        }
        __syncthreads();
    }
#pragma unroll
    for (int i = 0; i < 4; i++) {
        int gm = m0 + ty * 4 + i;
#pragma unroll
        for (int jj = 0; jj < 4; jj++) {
            int gn = n0 + tx * 4 + jj;
            float v = acc[i][jj];
            if (flags & 1) v = v / fmaxf(nx[gm] * ny[gn], 1e-12f);
            if ((flags & 2) && gm == gn) v = 0.f;
            Cmat[(size_t)gm * Ndim + gn] = v;
        }
    }
}

// column reduce over logits [N,C]
__global__ void k_colreduce(const float* __restrict__ logits, float* __restrict__ cmax,
                            float* __restrict__ csum) {
    __shared__ float col[Nn];
    __shared__ float red[256];
    int c = blockIdx.x;
    int tid = threadIdx.x;
    for (int n = tid; n < Nn; n += 256) col[n] = logits[(size_t)n * Cc + c];
    __syncthreads();
    float m = -FLT_MAX;
    for (int n = tid; n < Nn; n += 256) m = fmaxf(m, col[n]);
    red[tid] = m;
    __syncthreads();
    for (int st = 128; st > 0; st >>= 1) {
        if (tid < st) red[tid] = fmaxf(red[tid], red[tid + st]);
        __syncthreads();
    }
    float mx = red[0];
    __syncthreads();
    float s = 0.f;
    for (int n = tid; n < Nn; n += 256) s += __expf(col[n] - mx);
    red[tid] = s;
    __syncthreads();
    for (int st = 128; st > 0; st >>= 1) {
        if (tid < st) red[tid] += red[tid + st];
        __syncthreads();
    }
    if (tid == 0) { cmax[c] = mx; csum[c] = red[0]; }
}

// row softmax with validity mask, in place
__global__ void k_rowsoftmax(float* __restrict__ mat, const float* __restrict__ v, int W) {
    __shared__ float buf[Nn];
    __shared__ float red[256];
    int row = blockIdx.x;
    int tid = threadIdx.x;
    float* r = mat + (size_t)row * W;
    for (int i = tid; i < W; i += 256) buf[i] = (v[i] != 0.f) ? r[i] : -1e9f;
    __syncthreads();
    float m = -FLT_MAX;
    for (int i = tid; i < W; i += 256) m = fmaxf(m, buf[i]);
    red[tid] = m;
    __syncthreads();
    for (int st = 128; st > 0; st >>= 1) {
        if (tid < st) red[tid] = fmaxf(red[tid], red[tid + st]);
        __syncthreads();
    }
    float mx = red[0];
    __syncthreads();
    float s = 0.f;
    for (int i = tid; i < W; i += 256) s += __expf(buf[i] - mx);
    red[tid] = s;
    __syncthreads();
    for (int st = 128; st > 0; st >>= 1) {
        if (tid < st) red[tid] += red[tid + st];
        __syncthreads();
    }
    float inv = 1.f / red[0];
    for (int i = tid; i < W; i += 256)
        r[i] = (v[i] != 0.f) ? __expf(buf[i] - mx) * inv : 0.f;
}

// NN GEMM: C[M,128] = A[M,K] @ B[K,128]; BM=32, BK=32, 4x4 register tile
__global__ __launch_bounds__(256, 4) void k_gemm_nn(
    const float* __restrict__ A, const float* __restrict__ B,
    float* __restrict__ Cout, int K) {
    __shared__ float As[32][33];
    __shared__ float Bs[32][128];
    int m0 = blockIdx.x * 32;
    int tid = threadIdx.x;
    int ty = tid >> 5;
    int tx = tid & 31;
    float acc[4][4];
#pragma unroll
    for (int i = 0; i < 4; i++)
#pragma unroll
        for (int jj = 0; jj < 4; jj++) acc[i][jj] = 0.f;
    for (int ck = 0; ck < K; ck += 32) {
        for (int e = tid; e < 32 * 32; e += 256)
            As[e >> 5][e & 31] = A[(size_t)(m0 + (e >> 5)) * K + ck + (e & 31)];
        for (int e = tid; e < 32 * 128; e += 256)
            Bs[e >> 7][e & 127] = B[(size_t)(ck + (e >> 7)) * Hh + (e & 127)];
        __syncthreads();
#pragma unroll 8
        for (int kk = 0; kk < 32; kk++) {
            float4 b4 = *(const float4*)&Bs[kk][tx * 4];
            float a[4];
#pragma unroll
            for (int i = 0; i < 4; i++) a[i] = As[ty * 4 + i][kk];
#pragma unroll
            for (int i = 0; i < 4; i++) {
                acc[i][0] += a[i] * b4.x;
                acc[i][1] += a[i] * b4.y;
                acc[i][2] += a[i] * b4.z;
                acc[i][3] += a[i] * b4.w;
            }
        }
        __syncthreads();
    }
#pragma unroll
    for (int i = 0; i < 4; i++) {
        float4 v = make_float4(acc[i][0], acc[i][1], acc[i][2], acc[i][3]);
        *(float4*)&Cout[(size_t)(m0 + ty * 4 + i) * Hh + tx * 4] = v;
    }
}

// Dense H->H: C = (A0 [-A1] [-A2]) @ W^T + bias, optional leaky relu
__global__ void k_dense(const float* __restrict__ A0, const float* __restrict__ A1,
                        const float* __restrict__ A2, const float* __restrict__ W,
                        const float* __restrict__ bias, float* __restrict__ Cout, int leaky) {
    __shared__ float As[16][Hh];
    int m0 = blockIdx.x * 16;
    int tid = threadIdx.x;
    for (int e = tid; e < 16 * Hh; e += 128) {
        int m = e >> 7, h = e & 127;
        size_t idx = (size_t)(m0 + m) * Hh + h;
        float v = A0[idx];
        if (A1) v -= A1[idx];
        if (A2) v -= A2[idx];
        As[m][h] = v;
    }
    __syncthreads();
    int j = tid;
    float acc[16];
    float b = bias[j];
#pragma unroll
    for (int m = 0; m < 16; m++) acc[m] = b;
#pragma unroll 4
    for (int k = 0; k < Hh; k++) {
        float w = W[j * Hh + k];
#pragma unroll
        for (int m = 0; m < 16; m++) acc[m] += As[m][k] * w;
    }
#pragma unroll
    for (int m = 0; m < 16; m++) {
        float v = acc[m];
        if (leaky) v = v > 0.f ? v : 0.01f * v;
        Cout[(size_t)(m0 + m) * Hh + j] = v;
    }
}

// per-row top-K
__global__ void k_topk(const float* __restrict__ mat, float* __restrict__ topv,
                       int* __restrict__ topi) {
    __shared__ float vals[Nn];
    __shared__ float rv[256];
    __shared__ int ri[256];
    int row = blockIdx.x;
    int tid = threadIdx.x;
    for (int i = tid; i < Nn; i += 256) vals[i] = mat[(size_t)row * Nn + i];
    __syncthreads();
    for (int k = 0; k < Kt; k++) {
        float bv = -FLT_MAX;
        int bi = Nn;
        for (int i = tid; i < Nn; i += 256) {
            float v = vals[i];
            if (v > bv || (v == bv && i < bi)) { bv = v; bi = i; }
        }
        rv[tid] = bv; ri[tid] = bi;
        __syncthreads();
        for (int st = 128; st > 0; st >>= 1) {
            if (tid < st) {
                float ov = rv[tid + st]; int oi = ri[tid + st];
                if (ov > rv[tid] || (ov == rv[tid] && oi < ri[tid])) { rv[tid] = ov; ri[tid] = oi; }
            }
            __syncthreads();
        }
        if (tid == 0) {
            topv[row * Kt + k] = rv[0];
            topi[row * Kt + k] = ri[0];
            vals[ri[0]] = -FLT_MAX;
        }
        __syncthreads();
    }
}

// scatter: hidden_h[j] += val * h_shared[m]; colsum[j] += val
__global__ void k_scatter(const float* __restrict__ hsh, const float* __restrict__ topv,
                          const int* __restrict__ topi, float* __restrict__ hh,
                          float* __restrict__ colsum) {
    int m = blockIdx.x;
    int tid = threadIdx.x;
    float hv = hsh[(size_t)m * Hh + tid];
#pragma unroll
    for (int k = 0; k < Kt; k++) {
        int j = topi[m * Kt + k];
        float val = topv[m * Kt + k];
        atomicAdd(&hh[(size_t)j * Hh + tid], val * hv);
        if (tid == 0) atomicAdd(&colsum[j], val);
    }
}

// diag-add + v2/norm for hidden_h
__global__ void k_posthh(const float* __restrict__ hsh, const float* __restrict__ colsum,
                         const float* __restrict__ diag, float* __restrict__ hh,
                         float* __restrict__ v2, float* __restrict__ nhh) {
    __shared__ float rs[128], rq[128];
    int n = blockIdx.x;
    int tid = threadIdx.x;
    size_t idx = (size_t)n * Hh + tid;
    float v = hh[idx];
    if (colsum[n] != 0.f) {
        v += diag[n] * hsh[idx];
        hh[idx] = v;
    }
    rs[tid] = v;
    rq[tid] = v * v;
    __syncthreads();
    for (int st = 64; st > 0; st >>= 1) {
        if (tid < st) { rs[tid] += rs[tid + st]; rq[tid] += rq[tid + st]; }
        __syncthreads();
    }
    if (tid == 0) {
        v2[n] = (rs[0] != 0.f) ? 1.f : 0.f;
        nhh[n] = sqrtf(rq[0]);
    }
}

// final head
__global__ void k_final(const float* __restrict__ a, const float* __restrict__ b,
                        const float* __restrict__ c, const float* __restrict__ w,
                        const float* __restrict__ bo, float* __restrict__ out) {
    __shared__ float red[128];
    int n = blockIdx.x;
    int tid = threadIdx.x;
    size_t idx = (size_t)n * Hh + tid;
    red[tid] = (a[idx] + b[idx] + c[idx]) * w[tid];
    __syncthreads();
    for (int st = 64; st > 0; st >>= 1) {
        if (tid < st) red[tid] += red[tid + st];
        __syncthreads();
    }
    if (tid == 0) out[n] = red[0] + bo[0];
}

// ---------------------------------------------------------------------------
extern "C" void kernel_launch(void* const* d_in, const int* in_sizes, int n_in,
                              void* d_out, int out_size) {
    const float* x = (const float*)d_in[0];
    const float* cm = (const float*)d_in[1];
    const float* mv = (const float*)d_in[2];
    const float* wih0 = (const float*)d_in[3];
    const float* whh0 = (const float*)d_in[4];
    const float* bih0 = (const float*)d_in[5];
    const float* bhh0 = (const float*)d_in[6];
    const float* wih1 = (const float*)d_in[7];
    const float* whh1 = (const float*)d_in[8];
    const float* bih1 = (const float*)d_in[9];
    const float* bhh1 = (const float*)d_in[10];
    const float* w_ps = (const float*)d_in[11];
    const float* b_ps = (const float*)d_in[12];
    const float* w_hs = (const float*)d_in[13];
    const float* b_hs = (const float*)d_in[14];
    const float* w_ps_fore = (const float*)d_in[15];
    const float* b_ps_fore = (const float*)d_in[16];
    const float* w_hs_fore = (const float*)d_in[17];
    const float* b_hs_fore = (const float*)d_in[18];
    const float* w_ps_back = (const float*)d_in[19];
    const float* b_ps_back = (const float*)d_in[20];
    const float* w_hs_back = (const float*)d_in[21];
    const float* b_hs_back = (const float*)d_in[22];
    const float* w_indi = (const float*)d_in[23];
    const float* b_indi = (const float*)d_in[24];
    const float* w_out = (const float*)d_in[25];
    const float* b_out = (const float*)d_in[26];
    float* out = (float*)d_out;

    float* S;
    cudaGetSymbolAddress((void**)&S, g_buf);
    int* topi;
    cudaGetSymbolAddress((void**)&topi, g_topi);

    float* gx = S + OFF_GX;
    float* out0 = S + OFF_OUT0;
    float* xh = S + OFF_HA;
    float* wt0 = S + OFF_WT0;
    float* wt1 = S + OFF_WT1;
    float* wih1t = S + OFF_WIH1T;
    float* den = S + OFF_DEN;
    float* hidden = S + OFF_HIDDEN;
    float* v1 = S + OFF_V1;
    float* logits = S + OFF_LOGITS;
    float* cmax = S + OFF_CMAX;
    float* csum = S + OFF_CSUM;
    float* hidden2 = S + OFF_HIDDEN2;
    float* ny = S + OFF_NY;
    float* nx = S + OFF_NX;
    float* c2s = S + OFF_C2S;
    float* praw = S + OFF_PRAW;
    float* psh = S + OFF_PSH;
    float* pback = S + OFF_PBACK;
    float* outps = S + OFF_OUTPS;
    float* hsh = S + OFF_HSH;
    float* nhs = S + OFF_NHS;
    float* diag = S + OFF_DIAG;
    float* big = S + OFF_BIG;
    float* topv = S + OFF_TOPV;
    float* hh = S + OFF_HH;
    float* colsum = S + OFF_COLSUM;
    float* v2 = S + OFF_V2;
    float* nhh = S + OFF_NHH;
    float* hsiraw = S + OFF_HSIRAW;
    float* hsi = S + OFF_HSI;
    float* hback = S + OFF_HBACK;
    float* ouths = S + OFF_OUTHS;
    float* outind = S + OFF_OUTIN;
    float* xt = S + OFF_XT;
    float* wih0t = S + OFF_WIH0T;

    static bool attr_done = false;
    if (!attr_done) {
        cudaFuncSetAttribute(k_gru_wmma, cudaFuncAttributeMaxDynamicSharedMemorySize, SMEM_GRU);
        attr_done = true;
    }

    // 3 launches before the GRU (harness adds 2 -> ncu -s 5 captures GRU L0)
    k_prep_all<<<(G * Hh + 255) / 256, 256>>>(whh0, whh1, wih1, wih0, wt0, wt1,
                                              wih1t, wih0t, den, colsum);              // 1
    k_xt<<<(Nn * Tt * D24 + 255) / 256, 256>>>(x, xt, hh, wih0t);                      // 2
    k_gx0_tf32<<<dim3(Tt * Nn / 64, G / 64), 128>>>(xt, wih0t, bih0, gx);              // 3

    // GRU layers (tensor-core recurrence)
    k_gru_wmma<<<Nn / 32, 512, SMEM_GRU>>>(gx, wt0, bhh0, out0, nullptr);              // 4 <- profiled
    k_gemm_g3_tf32<<<dim3(Tt * Nn / 64, G / 64), 128>>>(out0, wih1t, bih1, gx);
    k_gru_wmma<<<Nn / 32, 512, SMEM_GRU>>>(gx, wt1, bhh1, nullptr, xh);

    // predefined-concept branch
    k_den<<<dim3(Cc / 128, 8), 128>>>(cm, mv, den);
    k_cagg<<<Cc / 8, 256>>>(cm, mv, den, nullptr, nullptr, nullptr, xh, hidden, v1, 0);
    k_gemm_nt<<<dim3(Cc / 64, Nn / 64), 256>>>(xh, hidden, nullptr, nullptr, logits, Cc, 0);
    k_colreduce<<<Cc, 256>>>(logits, cmax, csum);
    k_cagg<<<Cc / 8, 256>>>(cm, mv, den, logits, cmax, csum, xh, hidden2, ny, 1);
    k_subnorm<<<Nn, 128>>>(xh, nullptr, xh, nx, nullptr);
    k_gemm_nt<<<dim3(Cc / 64, Nn / 64), 256>>>(xh, hidden2, nx, ny, c2s, Cc, 1);
    k_rowsoftmax<<<Nn, 256>>>(c2s, v1, Cc);
    k_gemm_nn<<<Nn / 32, 256>>>(c2s, hidden2, praw, Cc);
    k_dense<<<Nn / 16, 128>>>(praw, nullptr, nullptr, w_ps, b_ps, psh, 0);
    k_dense<<<Nn / 16, 128>>>(psh, nullptr, nullptr, w_ps_back, b_ps_back, pback, 0);
    k_dense<<<Nn / 16, 128>>>(psh, nullptr, nullptr, w_ps_fore, b_ps_fore, outps, 1);

    // hidden-concept branch
    k_subnorm<<<Nn, 128>>>(xh, pback, hsh, nhs, diag);
    k_gemm_nt<<<dim3(Nn / 64, Nn / 64), 256>>>(hsh, hsh, nhs, nhs, big, Nn, 3);
    k_topk<<<Nn, 256>>>(big, topv, topi);
    k_scatter<<<Nn, 128>>>(hsh, topv, topi, hh, colsum);
    k_posthh<<<Nn, 128>>>(hsh, colsum, diag, hh, v2, nhh);
    k_gemm_nt<<<dim3(Nn / 64, Nn / 64), 256>>>(hsh, hh, nhs, nhh, big, Nn, 1);
    k_rowsoftmax<<<Nn, 256>>>(big, v2, Nn);
    k_gemm_nn<<<Nn / 32, 256>>>(big, hh, hsiraw, Nn);
    k_dense<<<Nn / 16, 128>>>(hsiraw, nullptr, nullptr, w_hs, b_hs, hsi, 0);
    k_dense<<<Nn / 16, 128>>>(hsi, nullptr, nullptr, w_hs_back, b_hs_back, hback, 0);
    k_dense<<<Nn / 16, 128>>>(hsi, nullptr, nullptr, w_hs_fore, b_hs_fore, ouths, 1);

    // individual branch + head
    k_dense<<<Nn / 16, 128>>>(xh, pback, hback, w_indi, b_indi, outind, 1);
    k_final<<<Nn, 128>>>(outps, ouths, outind, w_out, b_out, out);
}

// round 12
// speedup vs baseline: 1.7693x; 1.7693x over previous
#include <cuda_runtime.h>
#include <cuda_bf16.h>
#include <math.h>
#include <float.h>
#include <stdint.h>

namespace {
constexpr int Nn = 4096, Cc = 512, Hh = 128, Tt = 64, Dd = 20, Kt = 10, G = 384;
constexpr int RB = 28;          // rows per GRU block
constexpr int GRU_GRID = 147;   // 147*28 = 4116 >= 4096

constexpr size_t SZ_GX = (size_t)Tt * Nn * G;
constexpr size_t SZ_OUT0 = (size_t)Tt * Nn * Hh;
constexpr size_t SZ_NH = (size_t)Nn * Hh;
constexpr size_t SZ_WT = (size_t)Hh * G;
constexpr size_t SZ_CH = (size_t)Cc * Hh;
constexpr size_t SZ_NC = (size_t)Nn * Cc;
constexpr size_t SZ_BIG = (size_t)Nn * Nn;

constexpr size_t OFF_GX = 0;
constexpr size_t OFF_OUT0 = OFF_GX + SZ_GX;
constexpr size_t OFF_HA = OFF_OUT0 + SZ_OUT0;
constexpr size_t OFF_WT0 = OFF_HA + SZ_NH;
constexpr size_t OFF_WT1 = OFF_WT0 + SZ_WT;
constexpr size_t OFF_WIH1T = OFF_WT1 + SZ_WT;
constexpr size_t OFF_DEN = OFF_WIH1T + SZ_WT;
constexpr size_t OFF_HIDDEN = OFF_DEN + Cc;
constexpr size_t OFF_V1 = OFF_HIDDEN + SZ_CH;
constexpr size_t OFF_LOGITS = OFF_V1 + Cc;
constexpr size_t OFF_CMAX = OFF_LOGITS + SZ_NC;
constexpr size_t OFF_CSUM = OFF_CMAX + Cc;
constexpr size_t OFF_HIDDEN2 = OFF_CSUM + Cc;
constexpr size_t OFF_NY = OFF_HIDDEN2 + SZ_CH;
constexpr size_t OFF_NX = OFF_NY + Cc;
constexpr size_t OFF_C2S = OFF_NX + Nn;
constexpr size_t OFF_PRAW = OFF_C2S + SZ_NC;
constexpr size_t OFF_PSH = OFF_PRAW + SZ_NH;
constexpr size_t OFF_PBACK = OFF_PSH + SZ_NH;
constexpr size_t OFF_OUTPS = OFF_PBACK + SZ_NH;
constexpr size_t OFF_HSH = OFF_OUTPS + SZ_NH;
constexpr size_t OFF_NHS = OFF_HSH + SZ_NH;
constexpr size_t OFF_DIAG = OFF_NHS + Nn;
constexpr size_t OFF_BIG = OFF_DIAG + Nn;
constexpr size_t OFF_TOPV = OFF_BIG + SZ_BIG;
constexpr size_t OFF_HH = OFF_TOPV + (size_t)Nn * Kt;
constexpr size_t OFF_COLSUM = OFF_HH + SZ_NH;
constexpr size_t OFF_V2 = OFF_COLSUM + Nn;
constexpr size_t OFF_NHH = OFF_V2 + Nn;
constexpr size_t OFF_HSIRAW = OFF_NHH + Nn;
constexpr size_t OFF_HSI = OFF_HSIRAW + SZ_NH;
constexpr size_t OFF_HBACK = OFF_HSI + SZ_NH;
constexpr size_t OFF_OUTHS = OFF_HBACK + SZ_NH;
constexpr size_t OFF_OUTIN = OFF_OUTHS + SZ_NH;
constexpr size_t OFF_XT = OFF_OUTIN + SZ_NH;
constexpr size_t OFF_WIH0T = OFF_XT + (size_t)Tt * Nn * Dd;
constexpr size_t TOTAL = OFF_WIH0T + (size_t)Dd * G;

constexpr int SMEM_L = (128 * G + RB * Hh + RB * Dd) * 4;  // 213184 bytes
}  // namespace

__device__ float g_buf[TOTAL];
__device__ int g_topi[Nn * Kt];

__device__ __forceinline__ float fsig(float x) {
    return __fdividef(1.f, 1.f + __expf(-x));
}
__device__ __forceinline__ float ftanh(float x) {
    float y;
    asm("tanh.approx.f32 %0, %1;" : "=f"(y) : "f"(x));
    return y;
}

// ---------------------------------------------------------------------------
// prep: weight transposes + zero den/colsum (launch 1)
// ---------------------------------------------------------------------------
__global__ void k_prep_all(const float* __restrict__ w0, const float* __restrict__ w1,
                           const float* __restrict__ w2, const float* __restrict__ wi0,
                           float* __restrict__ t0, float* __restrict__ t1,
                           float* __restrict__ t2, float* __restrict__ ti0,
                           float* __restrict__ den, float* __restrict__ colsum) {
    int i = blockIdx.x * blockDim.x + threadIdx.x;
    if (i < G * Hh) {
        int r = i / Hh, c = i % Hh;
        t0[c * G + r] = w0[i];
        t1[c * G + r] = w1[i];
        t2[c * G + r] = w2[i];
    }
    if (i < G * Dd) {
        int r = i / Dd, c = i % Dd;
        ti0[c * G + r] = wi0[i];
    }
    if (i < Cc) den[i] = 0.f;
    if (i < Nn) colsum[i] = 0.f;
}

// x [N, D*T] -> xt [T, N, D]; zero hh (launch 2)
__global__ void k_xt(const float* __restrict__ x, float* __restrict__ xt,
                     float* __restrict__ hh) {
    int i = blockIdx.x * blockDim.x + threadIdx.x;
    if (i < Nn * Dd * Tt) {
        int t = i % Tt;
        int d = (i / Tt) % Dd;
        int n = i / (Tt * Dd);
        xt[((size_t)t * Nn + n) * Dd + d] = x[i];
    }
    if (i < (int)SZ_NH) hh[i] = 0.f;
}

// den[c] = sum_n cm[n,c]*mv[n] (launch 3)
__global__ void k_den(const float* __restrict__ cm, const float* __restrict__ mv,
                      float* __restrict__ den) {
    int c = blockIdx.x * 128 + threadIdx.x;
    int nb = blockIdx.y;
    float s = 0.f;
    for (int n = nb * 512; n < (nb + 1) * 512; n++) s += cm[(size_t)n * Cc + c] * mv[n];
    atomicAdd(&den[c], s);
}

// ---------------------------------------------------------------------------
// Persistent GRU layer: grid=147 (all SMs), 512 threads, 28 rows/block.
// whhT (192KB) cached in smem; h lives in smem across all 64 steps.
// ---------------------------------------------------------------------------
template <bool L0>
__global__ __launch_bounds__(512, 1) void k_gru_layer(
    const float* __restrict__ xin,  // L0: xt [T,N,D]; L1: gx [T,N,G]
    const float* __restrict__ wih0t, const float* __restrict__ bih0,
    const float* __restrict__ wt, const float* __restrict__ bhh,
    float* __restrict__ out0, float* __restrict__ xh) {
    extern __shared__ float sm[];
    float* ws = sm;                 // [128][384]
    float* hs = sm + 128 * G;       // [28][128]
    float* xs = hs + RB * Hh;       // [28][20]
    int tid = threadIdx.x;
    int j = tid & 127, rg = tid >> 7;  // rg 0..3
    int n0 = blockIdx.x * RB;
    int r0 = rg * 7;

    {
        const float4* s = (const float4*)wt;
        float4* d = (float4*)ws;
        for (int e = tid; e < 128 * G / 4; e += 512) d[e] = s[e];
    }
    for (int e = tid; e < RB * Hh; e += 512) hs[e] = 0.f;

    float br = bhh[j], bz = bhh[j + 128], bn = bhh[j + 256];
    float bir = 0.f, biz = 0.f, bin = 0.f;
    if (L0) { bir = bih0[j]; biz = bih0[j + 128]; bin = bih0[j + 256]; }

    for (int t = 0; t < Tt; t++) {
        if (L0) {
            const float* src = xin + ((size_t)t * Nn + n0) * Dd;
            for (int e = tid; e < RB * Dd; e += 512)
                xs[e] = (n0 + e / Dd < Nn) ? src[e] : 0.f;
        }
        __syncthreads();
        float ar[7], az[7], axn[7], ahn[7];
        if (L0) {
#pragma unroll
            for (int m = 0; m < 7; m++) {
                ar[m] = br + bir; az[m] = bz + biz; axn[m] = bin; ahn[m] = bn;
            }
#pragma unroll 4
            for (int d = 0; d < Dd; d++) {
                float wr = wih0t[d * G + j];
                float wz = wih0t[d * G + j + 128];
                float wn = wih0t[d * G + j + 256];
#pragma unroll
                for (int m = 0; m < 7; m++) {
                    float xv = xs[(r0 + m) * Dd + d];
                    ar[m] += xv * wr; az[m] += xv * wz; axn[m] += xv * wn;
                }
            }
        } else {
            const float* gp = xin + ((size_t)t * Nn + n0) * G;
#pragma unroll
            for (int m = 0; m < 7; m++) {
                bool ok = (n0 + r0 + m) < Nn;
                ar[m] = ok ? gp[(r0 + m) * G + j] + br : 0.f;
                az[m] = ok ? gp[(r0 + m) * G + j + 128] + bz : 0.f;
                axn[m] = ok ? gp[(r0 + m) * G + j + 256] : 0.f;
                ahn[m] = bn;
            }
        }
        for (int k = 0; k < Hh; k += 4) {
            float4 hv[7];
#pragma unroll
            for (int m = 0; m < 7; m++)
                hv[m] = *(const float4*)&hs[(r0 + m) * Hh + k];
#pragma unroll
            for (int kk = 0; kk < 4; kk++) {
                float wr = ws[(k + kk) * G + j];
                float wz = ws[(k + kk) * G + j + 128];
                float wn = ws[(k + kk) * G + j + 256];
#pragma unroll
                for (int m = 0; m < 7; m++) {
                    float h = (kk == 0) ? hv[m].x : (kk == 1) ? hv[m].y
                              : (kk == 2) ? hv[m].z : hv[m].w;
                    ar[m] += h * wr; az[m] += h * wz; ahn[m] += h * wn;
                }
            }
        }
        float hnew[7];
#pragma unroll
        for (int m = 0; m < 7; m++) {
            float r = fsig(ar[m]);
            float z = fsig(az[m]);
            float nc = ftanh(axn[m] + r * ahn[m]);
            float hold = hs[(r0 + m) * Hh + j];
            hnew[m] = (1.f - z) * nc + z * hold;
        }
        __syncthreads();
#pragma unroll
        for (int m = 0; m < 7; m++) {
            int n = n0 + r0 + m;
            hs[(r0 + m) * Hh + j] = hnew[m];
            if (n < Nn) {
                if (L0)
                    out0[((size_t)t * Nn + n) * Hh + j] = hnew[m];
                else if (t == Tt - 1)
                    xh[(size_t)n * Hh + j] = hnew[m];
            }
        }
    }
}

// ---------------------------------------------------------------------------
// gx1 = out0 @ wih1T + bih1   (M = T*N, 3-col-per-thread layout, TM=32)
// ---------------------------------------------------------------------------
__global__ __launch_bounds__(256, 2) void k_gemm_g3(
    const float* __restrict__ A, const float* __restrict__ WT,
    const float* __restrict__ bias, float* __restrict__ Cout) {
    __shared__ float As[32 * Hh];
    int tid = threadIdx.x;
    int j = tid & 127, rg = tid >> 7;
    int m0 = blockIdx.x * 32;
    {
        const float4* s = (const float4*)(A + (size_t)m0 * Hh);
        float4* d = (float4*)As;
        for (int e = tid; e < 32 * Hh / 4; e += 256) d[e] = s[e];
    }
    __syncthreads();
    int r0 = rg * 16;
    float ar[16], az[16], an[16];
#pragma unroll
    for (int m = 0; m < 16; m++) { ar[m] = 0.f; az[m] = 0.f; an[m] = 0.f; }
    for (int k = 0; k < Hh; k += 2) {
        float2 hv[16];
#pragma unroll
        for (int m = 0; m < 16; m++)
            hv[m] = *(const float2*)&As[(r0 + m) * Hh + k];
#pragma unroll
        for (int kk = 0; kk < 2; kk++) {
            float wr = WT[(k + kk) * G + j];
            float wz = WT[(k + kk) * G + j + 128];
            float wn = WT[(k + kk) * G + j + 256];
#pragma unroll
            for (int m = 0; m < 16; m++) {
                float h = kk ? hv[m].y : hv[m].x;
                ar[m] += h * wr; az[m] += h * wz; an[m] += h * wn;
            }
        }
    }
    float br = bias[j], bz = bias[j + 128], bn = bias[j + 256];
#pragma unroll
    for (int m = 0; m < 16; m++) {
        size_t base = (size_t)(m0 + r0 + m) * G;
        Cout[base + j] = ar[m] + br;
        Cout[base + j + 128] = az[m] + bz;
        Cout[base + j + 256] = an[m] + bn;
    }
}

// Weighted aggregation into [C,H]
__global__ void k_cagg(const float* __restrict__ cm, const float* __restrict__ mv,
                       const float* __restrict__ den, const float* __restrict__ logits,
                       const float* __restrict__ cmax, const float* __restrict__ csum,
                       const float* __restrict__ xh, float* __restrict__ outp,
                       float* __restrict__ aux, int mode) {
    __shared__ float xs[64][Hh];
    __shared__ float cs[64][8];
    __shared__ float red[256];
    int c0 = blockIdx.x * 8;
    int tid = threadIdx.x;
    int h = tid & 127, g = tid >> 7;
    float acc[4] = {0.f, 0.f, 0.f, 0.f};
    for (int nb = 0; nb < Nn; nb += 64) {
        for (int e = tid; e < 64 * Hh; e += 256)
            xs[e >> 7][e & 127] = xh[(size_t)(nb + (e >> 7)) * Hh + (e & 127)];
        for (int e = tid; e < 64 * 8; e += 256) {
            int nn = e >> 3, ci = e & 7;
            int n = nb + nn, c = c0 + ci;
            float coef;
            if (mode == 0) {
                float cv = cm[(size_t)n * Cc + c];
                coef = cv * mv[n] / (den[c] * cv + 1.f);
            } else {
                coef = __expf(logits[(size_t)n * Cc + c] - cmax[c]) / csum[c];
            }
            cs[nn][ci] = coef;
        }
        __syncthreads();
#pragma unroll 4
        for (int nn = 0; nn < 64; nn++) {
            float xv = xs[nn][h];
#pragma unroll
            for (int u = 0; u < 4; u++) acc[u] += cs[nn][g + 2 * u] * xv;
        }
        __syncthreads();
    }
#pragma unroll
    for (int u = 0; u < 4; u++) outp[(size_t)(c0 + g + 2 * u) * Hh + h] = acc[u];
    for (int u = 0; u < 4; u++) {
        red[tid] = (mode == 0) ? acc[u] : acc[u] * acc[u];
        __syncthreads();
        for (int st = 64; st > 0; st >>= 1) {
            if (h < st) red[tid] += red[tid + st];
            __syncthreads();
        }
        if (h == 0) {
            int c = c0 + g + 2 * u;
            aux[c] = (mode == 0) ? ((red[tid] != 0.f) ? 1.f : 0.f) : sqrtf(red[tid]);
        }
        __syncthreads();
    }
}

// Out = A [- B]; nrm = ||row||; diag = ss/max(ss,1e-12)
__global__ void k_subnorm(const float* __restrict__ A, const float* __restrict__ B,
                          float* __restrict__ Out, float* __restrict__ nrm,
                          float* __restrict__ diag) {
    __shared__ float red[128];
    int n = blockIdx.x;
    int tid = threadIdx.x;
    float v = A[(size_t)n * Hh + tid];
    if (B) v -= B[(size_t)n * Hh + tid];
    Out[(size_t)n * Hh + tid] = v;
    red[tid] = v * v;
    __syncthreads();
    for (int st = 64; st > 0; st >>= 1) {
        if (tid < st) red[tid] += red[tid + st];
        __syncthreads();
    }
    if (tid == 0) {
        float ss = red[0];
        nrm[n] = sqrtf(ss);
        if (diag) diag[n] = ss / fmaxf(ss, 1e-12f);
    }
}

// ---------------------------------------------------------------------------
// NT GEMM, K=128: 128x128 block tile, 8x8 per thread, k-major smem.
// flags: 1=cosine-normalize, 2=zero diag
// ---------------------------------------------------------------------------
__global__ __launch_bounds__(256) void k_gemm_nt(
    const float* __restrict__ A, const float* __restrict__ B,
    const float* __restrict__ nx, const float* __restrict__ ny,
    float* __restrict__ Cmat, int Ndim, int flags) {
    __shared__ float As[32][132];
    __shared__ float Bs[32][132];
    int m0 = blockIdx.y * 128, n0 = blockIdx.x * 128;
    int tid = threadIdx.x;
    int ty = tid >> 4, tx = tid & 15;  // 16x16 thread grid, 8x8 each
    float acc[8][8];
#pragma unroll
    for (int i = 0; i < 8; i++)
#pragma unroll
        for (int jj = 0; jj < 8; jj++) acc[i][jj] = 0.f;

    for (int kc = 0; kc < Hh; kc += 32) {
#pragma unroll
        for (int it = 0; it < 4; it++) {
            int e = (it * 256 + tid) * 4;
            int r = e >> 5, c = e & 31;
            float4 va = *(const float4*)&A[(size_t)(m0 + r) * Hh + kc + c];
            As[c][r] = va.x; As[c + 1][r] = va.y; As[c + 2][r] = va.z; As[c + 3][r] = va.w;
            float4 vb = *(const float4*)&B[(size_t)(n0 + r) * Hh + kc + c];
            Bs[c][r] = vb.x; Bs[c + 1][r] = vb.y; Bs[c + 2][r] = vb.z; Bs[c + 3][r] = vb.w;
        }
        __syncthreads();
#pragma unroll
        for (int kk = 0; kk < 32; kk++) {
            float4 a0 = *(const float4*)&As[kk][ty * 8];
            float4 a1 = *(const float4*)&As[kk][ty * 8 + 4];
            float4 b0 = *(const float4*)&Bs[kk][tx * 8];
            float4 b1 = *(const float4*)&Bs[kk][tx * 8 + 4];
            float a[8] = {a0.x, a0.y, a0.z, a0.w, a1.x, a1.y, a1.z, a1.w};
            float b[8] = {b0.x, b0.y, b0.z, b0.w, b1.x, b1.y, b1.z, b1.w};
#pragma unroll
            for (int i = 0; i < 8; i++)
#pragma unroll
                for (int jj = 0; jj < 8; jj++) acc[i][jj] += a[i] * b[jj];
        }
        __syncthreads();
    }
#pragma unroll
    for (int i = 0; i < 8; i++) {
        int gm = m0 + ty * 8 + i;
        float nxv = (flags & 1) ? nx[gm] : 1.f;
#pragma unroll
        for (int jj = 0; jj < 8; jj++) {
            int gn = n0 + tx * 8 + jj;
            float v = acc[i][jj];
            if (flags & 1) v = v / fmaxf(nxv * ny[gn], 1e-12f);
            if ((flags & 2) && gm == gn) v = 0.f;
            Cmat[(size_t)gm * Ndim + gn] = v;
        }
    }
}

// column reduce over logits [N,C]
__global__ void k_colreduce(const float* __restrict__ logits, float* __restrict__ cmax,
                            float* __restrict__ csum) {
    __shared__ float col[Nn];
    __shared__ float red[256];
    int c = blockIdx.x;
    int tid = threadIdx.x;
    for (int n = tid; n < Nn; n += 256) col[n] = logits[(size_t)n * Cc + c];
    __syncthreads();
    float m = -FLT_MAX;
    for (int n = tid; n < Nn; n += 256) m = fmaxf(m, col[n]);
    red[tid] = m;
    __syncthreads();
    for (int st = 128; st > 0; st >>= 1) {
        if (tid < st) red[tid] = fmaxf(red[tid], red[tid + st]);
        __syncthreads();
    }
    float mx = red[0];
    __syncthreads();
    float s = 0.f;
    for (int n = tid; n < Nn; n += 256) s += __expf(col[n] - mx);
    red[tid] = s;
    __syncthreads();
    for (int st = 128; st > 0; st >>= 1) {
        if (tid < st) red[tid] += red[tid + st];
        __syncthreads();
    }
    if (tid == 0) { cmax[c] = mx; csum[c] = red[0]; }
}

// row softmax with validity mask, in place
__global__ void k_rowsoftmax(float* __restrict__ mat, const float* __restrict__ v, int W) {
    __shared__ float buf[Nn];
    __shared__ float red[256];
    int row = blockIdx.x;
    int tid = threadIdx.x;
    float* r = mat + (size_t)row * W;
    for (int i = tid; i < W; i += 256) buf[i] = (v[i] != 0.f) ? r[i] : -1e9f;
    __syncthreads();
    float m = -FLT_MAX;
    for (int i = tid; i < W; i += 256) m = fmaxf(m, buf[i]);
    red[tid] = m;
    __syncthreads();
    for (int st = 128; st > 0; st >>= 1) {
        if (tid < st) red[tid] = fmaxf(red[tid], red[tid + st]);
        __syncthreads();
    }
    float mx = red[0];
    __syncthreads();
    float s = 0.f;
    for (int i = tid; i < W; i += 256) s += __expf(buf[i] - mx);
    red[tid] = s;
    __syncthreads();
    for (int st = 128; st > 0; st >>= 1) {
        if (tid < st) red[tid] += red[tid + st];
        __syncthreads();
    }
    float inv = 1.f / red[0];
    for (int i = tid; i < W; i += 256)
        r[i] = (v[i] != 0.f) ? __expf(buf[i] - mx) * inv : 0.f;
}

// ---------------------------------------------------------------------------
// NN GEMM: C[M,128] = A[M,K] @ B[K,128]; 32x128 tile, 4x4 per thread,
// k-major A (warp-broadcast), coalesced B.
// ---------------------------------------------------------------------------
__global__ __launch_bounds__(256) void k_gemm_nn(
    const float* __restrict__ A, const float* __restrict__ B,
    float* __restrict__ Cout, int K) {
    __shared__ float As[32][36];
    __shared__ float Bs[32][128];
    int m0 = blockIdx.x * 32;
    int tid = threadIdx.x;
    int ty = tid >> 5;   // 0..7 -> 4 rows each
    int tx = tid & 31;   // 0..31 -> 4 cols each
    float acc[4][4];
#pragma unroll
    for (int i = 0; i < 4; i++)
#pragma unroll
        for (int jj = 0; jj < 4; jj++) acc[i][jj] = 0.f;

    for (int ck = 0; ck < K; ck += 32) {
        {
            int e = tid * 4;
            int r = e >> 5, c = e & 31;
            float4 va = *(const float4*)&A[(size_t)(m0 + r) * K + ck + c];
            As[c][r] = va.x; As[c + 1][r] = va.y; As[c + 2][r] = va.z; As[c + 3][r] = va.w;
        }
#pragma unroll
        for (int it = 0; it < 4; it++) {
            int e = (it * 256 + tid) * 4;
            int kr = e >> 7, cc = e & 127;
            *(float4*)&Bs[kr][cc] = *(const float4*)&B[(size_t)(ck + kr) * Hh + cc];
        }
        __syncthreads();
#pragma unroll
        for (int kk = 0; kk < 32; kk++) {
            float4 a4 = *(const float4*)&As[kk][ty * 4];
            float4 b4 = *(const float4*)&Bs[kk][tx * 4];
            float a[4] = {a4.x, a4.y, a4.z, a4.w};
#pragma unroll
            for (int i = 0; i < 4; i++) {
                acc[i][0] += a[i] * b4.x;
                acc[i][1] += a[i] * b4.y;
                acc[i][2] += a[i] * b4.z;
                acc[i][3] += a[i] * b4.w;
            }
        }
        __syncthreads();
    }
#pragma unroll
    for (int i = 0; i < 4; i++) {
        float4 v = make_float4(acc[i][0], acc[i][1], acc[i][2], acc[i][3]);
        *(float4*)&Cout[(size_t)(m0 + ty * 4 + i) * Hh + tx * 4] = v;
    }
}

// Dense H->H: C = (A0 [-A1] [-A2]) @ W^T + bias, optional leaky relu
__global__ void k_dense(const float* __restrict__ A0, const float* __restrict__ A1,
                        const float* __restrict__ A2, const float* __restrict__ W,
                        const float* __restrict__ bias, float* __restrict__ Cout, int leaky) {
    __shared__ float As[16][Hh];
    int m0 = blockIdx.x * 16;
    int tid = threadIdx.x;
    for (int e = tid; e < 16 * Hh; e += 128) {
        int m = e >> 7, h = e & 127;
        size_t idx = (size_t)(m0 + m) * Hh + h;
        float v = A0[idx];
        if (A1) v -= A1[idx];
        if (A2) v -= A2[idx];
        As[m][h] = v;
    }
    __syncthreads();
    int j = tid;
    float acc[16];
    float b = bias[j];
#pragma unroll
    for (int m = 0; m < 16; m++) acc[m] = b;
#pragma unroll 4
    for (int k = 0; k < Hh; k++) {
        float w = W[j * Hh + k];
#pragma unroll
        for (int m = 0; m < 16; m++) acc[m] += As[m][k] * w;
    }
#pragma unroll
    for (int m = 0; m < 16; m++) {
        float v = acc[m];
        if (leaky) v = v > 0.f ? v : 0.01f * v;
        Cout[(size_t)(m0 + m) * Hh + j] = v;
    }
}

// per-row top-K
__global__ void k_topk(const float* __restrict__ mat, float* __restrict__ topv,
                       int* __restrict__ topi) {
    __shared__ float vals[Nn];
    __shared__ float rv[256];
    __shared__ int ri[256];
    int row = blockIdx.x;
    int tid = threadIdx.x;
    for (int i = tid; i < Nn; i += 256) vals[i] = mat[(size_t)row * Nn + i];
    __syncthreads();
    for (int k = 0; k < Kt; k++) {
        float bv = -FLT_MAX;
        int bi = Nn;
        for (int i = tid; i < Nn; i += 256) {
            float v = vals[i];
            if (v > bv || (v == bv && i < bi)) { bv = v; bi = i; }
        }
        rv[tid] = bv; ri[tid] = bi;
        __syncthreads();
        for (int st = 128; st > 0; st >>= 1) {
            if (tid < st) {
                float ov = rv[tid + st]; int oi = ri[tid + st];
                if (ov > rv[tid] || (ov == rv[tid] && oi < ri[tid])) { rv[tid] = ov; ri[tid] = oi; }
            }
            __syncthreads();
        }
        if (tid == 0) {
            topv[row * Kt + k] = rv[0];
            topi[row * Kt + k] = ri[0];
            vals[ri[0]] = -FLT_MAX;
        }
        __syncthreads();
    }
}

// scatter: hidden_h[j] += val * h_shared[m]; colsum[j] += val
__global__ void k_scatter(const float* __restrict__ hsh, const float* __restrict__ topv,
                          const int* __restrict__ topi, float* __restrict__ hh,
                          float* __restrict__ colsum) {
    int m = blockIdx.x;
    int tid = threadIdx.x;
    float hv = hsh[(size_t)m * Hh + tid];
#pragma unroll
    for (int k = 0; k < Kt; k++) {
        int j = topi[m * Kt + k];
        float val = topv[m * Kt + k];
        atomicAdd(&hh[(size_t)j * Hh + tid], val * hv);
        if (tid == 0) atomicAdd(&colsum[j], val);
    }
}

// diag-add + v2/norm for hidden_h
__global__ void k_posthh(const float* __restrict__ hsh, const float* __restrict__ colsum,
                         const float* __restrict__ diag, float* __restrict__ hh,
                         float* __restrict__ v2, float* __restrict__ nhh) {
    __shared__ float rs[128], rq[128];
    int n = blockIdx.x;
    int tid = threadIdx.x;
    size_t idx = (size_t)n * Hh + tid;
    float v = hh[idx];
    if (colsum[n] != 0.f) {
        v += diag[n] * hsh[idx];
        hh[idx] = v;
    }
    rs[tid] = v;
    rq[tid] = v * v;
    __syncthreads();
    for (int st = 64; st > 0; st >>= 1) {
        if (tid < st) { rs[tid] += rs[tid + st]; rq[tid] += rq[tid + st]; }
        __syncthreads();
    }
    if (tid == 0) {
        v2[n] = (rs[0] != 0.f) ? 1.f : 0.f;
        nhh[n] = sqrtf(rq[0]);
    }
}

// final head
__global__ void k_final(const float* __restrict__ a, const float* __restrict__ b,
                        const float* __restrict__ c, const float* __restrict__ w,
                        const float* __restrict__ bo, float* __restrict__ out) {
    __shared__ float red[128];
    int n = blockIdx.x;
    int tid = threadIdx.x;
    size_t idx = (size_t)n * Hh + tid;
    red[tid] = (a[idx] + b[idx] + c[idx]) * w[tid];
    __syncthreads();
    for (int st = 64; st > 0; st >>= 1) {
        if (tid < st) red[tid] += red[tid + st];
        __syncthreads();
    }
    if (tid == 0) out[n] = red[0] + bo[0];
}

// ---------------------------------------------------------------------------
extern "C" void kernel_launch(void* const* d_in, const int* in_sizes, int n_in,
                              void* d_out, int out_size) {
    const float* x = (const float*)d_in[0];
    const float* cm = (const float*)d_in[1];
    const float* mv = (const float*)d_in[2];
    const float* wih0 = (const float*)d_in[3];
    const float* whh0 = (const float*)d_in[4];
    const float* bih0 = (const float*)d_in[5];
    const float* bhh0 = (const float*)d_in[6];
    const float* wih1 = (const float*)d_in[7];
    const float* whh1 = (const float*)d_in[8];
    const float* bih1 = (const float*)d_in[9];
    const float* bhh1 = (const float*)d_in[10];
    const float* w_ps = (const float*)d_in[11];
    const float* b_ps = (const float*)d_in[12];
    const float* w_hs = (const float*)d_in[13];
    const float* b_hs = (const float*)d_in[14];
    const float* w_ps_fore = (const float*)d_in[15];
    const float* b_ps_fore = (const float*)d_in[16];
    const float* w_hs_fore = (const float*)d_in[17];
    const float* b_hs_fore = (const float*)d_in[18];
    const float* w_ps_back = (const float*)d_in[19];
    const float* b_ps_back = (const float*)d_in[20];
    const float* w_hs_back = (const float*)d_in[21];
    const float* b_hs_back = (const float*)d_in[22];
    const float* w_indi = (const float*)d_in[23];
    const float* b_indi = (const float*)d_in[24];
    const float* w_out = (const float*)d_in[25];
    const float* b_out = (const float*)d_in[26];
    float* out = (float*)d_out;

    float* S;
    cudaGetSymbolAddress((void**)&S, g_buf);
    int* topi;
    cudaGetSymbolAddress((void**)&topi, g_topi);

    float* gx = S + OFF_GX;
    float* out0 = S + OFF_OUT0;
    float* xh = S + OFF_HA;
    float* wt0 = S + OFF_WT0;
    float* wt1 = S + OFF_WT1;
    float* wih1t = S + OFF_WIH1T;
    float* den = S + OFF_DEN;
    float* hidden = S + OFF_HIDDEN;
    float* v1 = S + OFF_V1;
    float* logits = S + OFF_LOGITS;
    float* cmax = S + OFF_CMAX;
    float* csum = S + OFF_CSUM;
    float* hidden2 = S + OFF_HIDDEN2;
    float* ny = S + OFF_NY;
    float* nx = S + OFF_NX;
    float* c2s = S + OFF_C2S;
    float* praw = S + OFF_PRAW;
    float* psh = S + OFF_PSH;
    float* pback = S + OFF_PBACK;
    float* outps = S + OFF_OUTPS;
    float* hsh = S + OFF_HSH;
    float* nhs = S + OFF_NHS;
    float* diag = S + OFF_DIAG;
    float* big = S + OFF_BIG;
    float* topv = S + OFF_TOPV;
    float* hh = S + OFF_HH;
    float* colsum = S + OFF_COLSUM;
    float* v2 = S + OFF_V2;
    float* nhh = S + OFF_NHH;
    float* hsiraw = S + OFF_HSIRAW;
    float* hsi = S + OFF_HSI;
    float* hback = S + OFF_HBACK;
    float* ouths = S + OFF_OUTHS;
    float* outind = S + OFF_OUTIN;
    float* xt = S + OFF_XT;
    float* wih0t = S + OFF_WIH0T;

    static bool attr_done = false;
    if (!attr_done) {
        cudaFuncSetAttribute(k_gru_layer<true>, cudaFuncAttributeMaxDynamicSharedMemorySize, SMEM_L);
        cudaFuncSetAttribute(k_gru_layer<false>, cudaFuncAttributeMaxDynamicSharedMemorySize, SMEM_L);
        attr_done = true;
    }

    // 3 launches before the GRU (harness adds 2 -> ncu -s 5 captures GRU L0)
    k_prep_all<<<(G * Hh + 255) / 256, 256>>>(whh0, whh1, wih1, wih0, wt0, wt1,
                                              wih1t, wih0t, den, colsum);      // 1
    k_xt<<<(Nn * Dd * Tt + 255) / 256, 256>>>(x, xt, hh);                      // 2
    k_den<<<dim3(Cc / 128, 8), 128>>>(cm, mv, den);                            // 3

    // GRU: persistent layer kernels on all 148 SMs
    k_gru_layer<true><<<GRU_GRID, 512, SMEM_L>>>(xt, wih0t, bih0, wt0, bhh0, out0, nullptr);  // 4 <- profiled
    k_gemm_g3<<<(Tt * Nn) / 32, 256>>>(out0, wih1t, bih1, gx);
    k_gru_layer<false><<<GRU_GRID, 512, SMEM_L>>>(gx, nullptr, nullptr, wt1, bhh1, nullptr, xh);

    // predefined-concept branch
    k_cagg<<<Cc / 8, 256>>>(cm, mv, den, nullptr, nullptr, nullptr, xh, hidden, v1, 0);
    k_gemm_nt<<<dim3(Cc / 128, Nn / 128), 256>>>(xh, hidden, nullptr, nullptr, logits, Cc, 0);
    k_colreduce<<<Cc, 256>>>(logits, cmax, csum);
    k_cagg<<<Cc / 8, 256>>>(cm, mv, den, logits, cmax, csum, xh, hidden2, ny, 1);
    k_subnorm<<<Nn, 128>>>(xh, nullptr, xh, nx, nullptr);
    k_gemm_nt<<<dim3(Cc / 128, Nn / 128), 256>>>(xh, hidden2, nx, ny, c2s, Cc, 1);
    k_rowsoftmax<<<Nn, 256>>>(c2s, v1, Cc);
    k_gemm_nn<<<Nn / 32, 256>>>(c2s, hidden2, praw, Cc);
    k_dense<<<Nn / 16, 128>>>(praw, nullptr, nullptr, w_ps, b_ps, psh, 0);
    k_dense<<<Nn / 16, 128>>>(psh, nullptr, nullptr, w_ps_back, b_ps_back, pback, 0);
    k_dense<<<Nn / 16, 128>>>(psh, nullptr, nullptr, w_ps_fore, b_ps_fore, outps, 1);

    // hidden-concept branch
    k_subnorm<<<Nn, 128>>>(xh, pback, hsh, nhs, diag);
    k_gemm_nt<<<dim3(Nn / 128, Nn / 128), 256>>>(hsh, hsh, nhs, nhs, big, Nn, 3);
    k_topk<<<Nn, 256>>>(big, topv, topi);
    k_scatter<<<Nn, 128>>>(hsh, topv, topi, hh, colsum);
    k_posthh<<<Nn, 128>>>(hsh, colsum, diag, hh, v2, nhh);
    k_gemm_nt<<<dim3(Nn / 128, Nn / 128), 256>>>(hsh, hh, nhs, nhh, big, Nn, 1);
    k_rowsoftmax<<<Nn, 256>>>(big, v2, Nn);
    k_gemm_nn<<<Nn / 32, 256>>>(big, hh, hsiraw, Nn);
    k_dense<<<Nn / 16, 128>>>(hsiraw, nullptr, nullptr, w_hs, b_hs, hsi, 0);
    k_dense<<<Nn / 16, 128>>>(hsi, nullptr, nullptr, w_hs_back, b_hs_back, hback, 0);
    k_dense<<<Nn / 16, 128>>>(hsi, nullptr, nullptr, w_hs_fore, b_hs_fore, ouths, 1);

    // individual branch + head
    k_dense<<<Nn / 16, 128>>>(xh, pback, hback, w_indi, b_indi, outind, 1);
    k_final<<<Nn, 128>>>(outps, ouths, outind, w_out, b_out, out);
}